// round 3
// baseline (speedup 1.0000x reference)
#include <cuda_runtime.h>

#define N   8192
#define DIM 128
#define E   262144

// Scratch (device globals -- allocation-free per harness rules)
__device__ float g_inv_nrm[N];
__device__ float g_dis[N];          // rsqrt(deg) incl. self loop
__device__ int   g_cnt[N];          // in-degree histogram (excl. self loop)
__device__ int   g_start[N];        // CSR start offsets
__device__ int   g_cursor[N];       // bump cursors for fill
__device__ int   g_csr[E];          // CSR: source node per edge slot
__device__ float g_M[DIM * DIM];    // Y^T x
__device__ float g_dxw[N * DIM];    // (x @ W) * dis[row]

// ----------------- K1: zero cnt + zero M + row inverse norms (fused)
__global__ void k_setup(const float* __restrict__ x) {
    int tid = threadIdx.x;
    int gi = blockIdx.x * 256 + tid;
    if (gi < DIM * DIM) g_M[gi] = 0.f;
    if (gi < N) g_cnt[gi] = 0;
    int w = tid >> 5, lane = tid & 31;
    int row = blockIdx.x * 8 + w;
    float4 v = ((const float4*)x)[row * 32 + lane];
    float s = v.x * v.x + v.y * v.y + v.z * v.z + v.w * v.w;
    #pragma unroll
    for (int o = 16; o; o >>= 1) s += __shfl_xor_sync(0xffffffffu, s, o);
    if (lane == 0) g_inv_nrm[row] = rsqrtf(s);
}

// ----------------- K2: in-degree histogram, 4 edges/thread
__global__ void k_hist(const int* __restrict__ ei) {
    int i = blockIdx.x * blockDim.x + threadIdx.x;
    int4 c = ((const int4*)(ei + E))[i];
    atomicAdd(&g_cnt[c.x], 1);
    atomicAdd(&g_cnt[c.y], 1);
    atomicAdd(&g_cnt[c.z], 1);
    atomicAdd(&g_cnt[c.w], 1);
}

// ----------------- K3: exclusive scan over 8192 counters + dis (1 block)
__global__ void k_scan() {
    __shared__ int warp_sums[32];
    int tid = threadIdx.x;           // 1024 threads, 8 counters each
    int base = tid * 8;
    int c[8], s = 0;
    #pragma unroll
    for (int j = 0; j < 8; j++) { c[j] = g_cnt[base + j]; s += c[j]; }
    int lane = tid & 31, w = tid >> 5;
    int v = s;
    #pragma unroll
    for (int o = 1; o < 32; o <<= 1) {
        int t = __shfl_up_sync(0xffffffffu, v, o);
        if (lane >= o) v += t;
    }
    if (lane == 31) warp_sums[w] = v;
    __syncthreads();
    if (w == 0) {
        int ws = warp_sums[lane];
        #pragma unroll
        for (int o = 1; o < 32; o <<= 1) {
            int t = __shfl_up_sync(0xffffffffu, ws, o);
            if (lane >= o) ws += t;
        }
        warp_sums[lane] = ws;
    }
    __syncthreads();
    int excl = v - s + (w > 0 ? warp_sums[w - 1] : 0);
    int run = excl;
    #pragma unroll
    for (int j = 0; j < 8; j++) {
        g_start[base + j]  = run;
        g_cursor[base + j] = run;
        g_dis[base + j]    = rsqrtf((float)(c[j] + 1));   // + self loop
        run += c[j];
    }
}

// ----------------- K4: CSR fill, 4 edges/thread
__global__ void k_fill(const int* __restrict__ ei) {
    int i = blockIdx.x * blockDim.x + threadIdx.x;
    int4 r = ((const int4*)ei)[i];
    int4 c = ((const int4*)(ei + E))[i];
    g_csr[atomicAdd(&g_cursor[c.x], 1)] = r.x;
    g_csr[atomicAdd(&g_cursor[c.y], 1)] = r.y;
    g_csr[atomicAdd(&g_cursor[c.z], 1)] = r.z;
    g_csr[atomicAdd(&g_cursor[c.w], 1)] = r.w;
}

// ----------------- K5: M = Y^T x  (128x128), 8x8 register tiles + atomics
__global__ void k_maccum(const float* __restrict__ x) {
    __shared__ float xs[8][DIM];
    __shared__ float invs[8];
    int tid = threadIdx.x;
    int tx = tid & 15, ty = tid >> 4;
    int k0 = ty * 8, d0 = tx * 8;
    float acc[8][8] = {};
    int row_base = blockIdx.x * 64;
    for (int p = 0; p < 8; p++) {
        int r0 = row_base + p * 8;
        {
            int rr = tid >> 5, cc = tid & 31;
            float4 v = ((const float4*)x)[(r0 + rr) * 32 + cc];
            ((float4*)&xs[rr][0])[cc] = v;
        }
        if (tid < 8) invs[tid] = g_inv_nrm[r0 + tid];
        __syncthreads();
        #pragma unroll
        for (int r = 0; r < 8; r++) {
            float inv = invs[r];
            float yk[8], xd[8];
            #pragma unroll
            for (int j = 0; j < 8; j++) yk[j] = xs[r][k0 + j] * inv;
            #pragma unroll
            for (int l = 0; l < 8; l++) xd[l] = xs[r][d0 + l];
            #pragma unroll
            for (int j = 0; j < 8; j++)
                #pragma unroll
                for (int l = 0; l < 8; l++)
                    acc[j][l] += yk[j] * xd[l];
        }
        __syncthreads();
    }
    #pragma unroll
    for (int j = 0; j < 8; j++)
        #pragma unroll
        for (int l = 0; l < 8; l++)
            atomicAdd(&g_M[(k0 + j) * DIM + (d0 + l)], acc[j][l]);
}

// ----------------- K6: dxw = (x @ W) * dis[row], warp per row
__global__ void k_dxw(const float* __restrict__ x, const float* __restrict__ W) {
    extern __shared__ float sm6[];
    float* Ws   = sm6;
    float* rows = sm6 + DIM * DIM;
    int tid = threadIdx.x;
    for (int i = tid; i < (DIM * DIM) / 4; i += 256)
        ((float4*)Ws)[i] = ((const float4*)W)[i];
    __syncthreads();
    int w = tid >> 5, lane = tid & 31;
    int row = blockIdx.x * 8 + w;
    float* myrow = rows + w * DIM;
    float4 xv = ((const float4*)x)[row * 32 + lane];
    ((float4*)myrow)[lane] = xv;
    __syncwarp();
    float4 acc = make_float4(0.f, 0.f, 0.f, 0.f);
    #pragma unroll 16
    for (int k = 0; k < DIM; k++) {
        float xk = myrow[k];
        float4 wv = ((float4*)Ws)[k * 32 + lane];
        acc.x += xk * wv.x; acc.y += xk * wv.y;
        acc.z += xk * wv.z; acc.w += xk * wv.w;
    }
    float di = g_dis[row];
    acc.x *= di; acc.y *= di; acc.z *= di; acc.w *= di;
    ((float4*)g_dxw)[row * 32 + lane] = acc;
}

// ----------------- K7: CSR gather + gate + epilogue (warp per node)
__global__ void k_final(const float* __restrict__ x, const float* __restrict__ b,
                        float* __restrict__ out) {
    extern __shared__ float sm8[];
    float* Ms   = sm8;                 // 16384
    float* rows = sm8 + DIM * DIM;     // 8*128
    float* bs   = rows + 8 * DIM;      // 128
    int tid = threadIdx.x;
    for (int i = tid; i < (DIM * DIM) / 4; i += 256)
        ((float4*)Ms)[i] = ((const float4*)g_M)[i];
    if (tid < 32) ((float4*)bs)[tid] = ((const float4*)b)[tid];
    __syncthreads();
    int w = tid >> 5, lane = tid & 31;
    int node = blockIdx.x * 8 + w;
    float inv = g_inv_nrm[node];
    float* myrow = rows + w * DIM;
    float4 xv = ((const float4*)x)[node * 32 + lane];
    xv.x *= inv; xv.y *= inv; xv.z *= inv; xv.w *= inv;
    ((float4*)myrow)[lane] = xv;
    __syncwarp();

    // gate = sigmoid(y . M)
    float4 a = make_float4(0.f, 0.f, 0.f, 0.f);
    #pragma unroll 16
    for (int k = 0; k < DIM; k++) {
        float yk = myrow[k];
        float4 mv = ((float4*)Ms)[k * 32 + lane];
        a.x += yk * mv.x; a.y += yk * mv.y;
        a.z += yk * mv.z; a.w += yk * mv.w;
    }
    a.x = 1.f / (1.f + __expf(-a.x));
    a.y = 1.f / (1.f + __expf(-a.y));
    a.z = 1.f / (1.f + __expf(-a.z));
    a.w = 1.f / (1.f + __expf(-a.w));

    // gather neighbors (self-loop term = own dxw row)
    int s0  = g_start[node];
    int cnt = g_cnt[node];
    float4 acc = ((const float4*)g_dxw)[node * 32 + lane];
    for (int base = 0; base < cnt; base += 32) {
        int rem = cnt - base;
        int idx = (lane < rem) ? g_csr[s0 + base + lane] : 0;
        int m = rem < 32 ? rem : 32;
        #pragma unroll 4
        for (int j = 0; j < m; j++) {
            int src = __shfl_sync(0xffffffffu, idx, j);
            float4 v = ((const float4*)g_dxw)[src * 32 + lane];
            acc.x += v.x; acc.y += v.y; acc.z += v.z; acc.w += v.w;
        }
    }
    float di = g_dis[node];
    float4 bb = ((float4*)bs)[lane];
    float4 o;
    o.x = (acc.x * di + bb.x) * a.x;
    o.y = (acc.y * di + bb.y) * a.y;
    o.z = (acc.z * di + bb.z) * a.z;
    o.w = (acc.w * di + bb.w) * a.w;
    ((float4*)out)[node * 32 + lane] = o;
}

// ---------------------------------------------------------------- launcher
extern "C" void kernel_launch(void* const* d_in, const int* in_sizes, int n_in,
                              void* d_out, int out_size) {
    const float* x  = (const float*)d_in[0];
    const int*   ei = (const int*)d_in[1];
    const float* W  = (const float*)d_in[2];
    const float* b  = (const float*)d_in[3];
    float* out = (float*)d_out;

    const int SMEM6 = (DIM * DIM + 8 * DIM) * 4;        // 69632
    const int SMEM8 = (DIM * DIM + 8 * DIM + DIM) * 4;  // 70144
    cudaFuncSetAttribute(k_dxw,   cudaFuncAttributeMaxDynamicSharedMemorySize, SMEM6);
    cudaFuncSetAttribute(k_final, cudaFuncAttributeMaxDynamicSharedMemorySize, SMEM8);

    k_setup<<<1024, 256>>>(x);
    k_hist<<<E / 1024, 256>>>(ei);
    k_scan<<<1, 1024>>>();
    k_fill<<<E / 1024, 256>>>(ei);
    k_maccum<<<128, 256>>>(x);
    k_dxw<<<N / 8, 256, SMEM6>>>(x, W);
    k_final<<<N / 8, 256, SMEM8>>>(x, b, out);
}

// round 4
// speedup vs baseline: 1.4427x; 1.4427x over previous
#include <cuda_runtime.h>

#define N   8192
#define DIM 128
#define E   262144
#define ASTR 132   // padded A row stride (floats): conflict-free broadcast reads

// Scratch (device globals -- allocation-free per harness rules)
__device__ float g_inv_nrm[N];
__device__ float g_dis[N];          // rsqrt(deg+1)
__device__ int   g_cnt[N];          // in-degree histogram (excl. self loop)
__device__ int   g_start[N];        // CSR start offsets
__device__ int   g_cursor[N];       // bump cursors for fill
__device__ int   g_csr[E];          // CSR: source node per edge slot
__device__ float g_M[DIM * DIM];    // Y^T x
__device__ float g_dxw[N * DIM];    // (x @ W) * dis[row]
__device__ float g_gate[N * DIM];   // sigmoid(y . M)

// ----------------- K1: zero cnt + zero M + row inverse norms (fused)
__global__ void k_setup(const float* __restrict__ x) {
    int tid = threadIdx.x;
    int gi = blockIdx.x * 256 + tid;
    if (gi < DIM * DIM) g_M[gi] = 0.f;
    if (gi < N) g_cnt[gi] = 0;
    int w = tid >> 5, lane = tid & 31;
    int row = blockIdx.x * 8 + w;
    float4 v = ((const float4*)x)[row * 32 + lane];
    float s = v.x * v.x + v.y * v.y + v.z * v.z + v.w * v.w;
    #pragma unroll
    for (int o = 16; o; o >>= 1) s += __shfl_xor_sync(0xffffffffu, s, o);
    if (lane == 0) g_inv_nrm[row] = rsqrtf(s);
}

// ----------------- K2: in-degree histogram, 1 edge/thread (wide grid)
__global__ void k_hist(const int* __restrict__ ei) {
    int i = blockIdx.x * blockDim.x + threadIdx.x;
    if (i < E) atomicAdd(&g_cnt[__ldg(&ei[E + i])], 1);
}

// ----------------- K3: exclusive scan over 8192 counters + dis (1 block)
__global__ void k_scan() {
    __shared__ int warp_sums[32];
    int tid = threadIdx.x;           // 1024 threads, 8 counters each
    int base = tid * 8;
    int c[8], s = 0;
    #pragma unroll
    for (int j = 0; j < 8; j++) { c[j] = g_cnt[base + j]; s += c[j]; }
    int lane = tid & 31, w = tid >> 5;
    int v = s;
    #pragma unroll
    for (int o = 1; o < 32; o <<= 1) {
        int t = __shfl_up_sync(0xffffffffu, v, o);
        if (lane >= o) v += t;
    }
    if (lane == 31) warp_sums[w] = v;
    __syncthreads();
    if (w == 0) {
        int ws = warp_sums[lane];
        #pragma unroll
        for (int o = 1; o < 32; o <<= 1) {
            int t = __shfl_up_sync(0xffffffffu, ws, o);
            if (lane >= o) ws += t;
        }
        warp_sums[lane] = ws;
    }
    __syncthreads();
    int excl = v - s + (w > 0 ? warp_sums[w - 1] : 0);
    int run = excl;
    #pragma unroll
    for (int j = 0; j < 8; j++) {
        g_start[base + j]  = run;
        g_cursor[base + j] = run;
        g_dis[base + j]    = rsqrtf((float)(c[j] + 1));   // + self loop
        run += c[j];
    }
}

// ----------------- K4: CSR fill, 1 edge/thread (wide grid)
__global__ void k_fill(const int* __restrict__ ei) {
    int i = blockIdx.x * blockDim.x + threadIdx.x;
    if (i < E) {
        int r = __ldg(&ei[i]);
        int c = __ldg(&ei[E + i]);
        g_csr[atomicAdd(&g_cursor[c], 1)] = r;
    }
}

// ----------------- K5: M = Y^T x  (128x128), 8x8 register tiles + atomics
__global__ void k_maccum(const float* __restrict__ x) {
    __shared__ float xs[8][DIM];
    __shared__ float invs[8];
    int tid = threadIdx.x;
    int tx = tid & 15, ty = tid >> 4;
    int k0 = ty * 8, d0 = tx * 8;
    float acc[8][8] = {};
    int row_base = blockIdx.x * 64;
    for (int p = 0; p < 8; p++) {
        int r0 = row_base + p * 8;
        {
            int rr = tid >> 5, cc = tid & 31;
            float4 v = ((const float4*)x)[(r0 + rr) * 32 + cc];
            ((float4*)&xs[rr][0])[cc] = v;
        }
        if (tid < 8) invs[tid] = g_inv_nrm[r0 + tid];
        __syncthreads();
        #pragma unroll
        for (int r = 0; r < 8; r++) {
            float inv = invs[r];
            float yk[8], xd[8];
            #pragma unroll
            for (int j = 0; j < 8; j++) yk[j] = xs[r][k0 + j] * inv;
            #pragma unroll
            for (int l = 0; l < 8; l++) xd[l] = xs[r][d0 + l];
            #pragma unroll
            for (int j = 0; j < 8; j++)
                #pragma unroll
                for (int l = 0; l < 8; l++)
                    acc[j][l] += yk[j] * xd[l];
        }
        __syncthreads();
    }
    #pragma unroll
    for (int j = 0; j < 8; j++)
        #pragma unroll
        for (int l = 0; l < 8; l++)
            atomicAdd(&g_M[(k0 + j) * DIM + (d0 + l)], acc[j][l]);
}

// ----------------- K6: register-tiled GEMM P = x @ (W or M), fused epilogue
// grid (64, 2): blockIdx.x = 128-row tile, blockIdx.y: 0 -> dxw, 1 -> gate.
// 256 threads, 8x8 outputs each. As row-major padded (broadcast-friendly).
__global__ void k_gemm(const float* __restrict__ x, const float* __restrict__ W) {
    extern __shared__ float sm[];
    float* As = sm;                    // [128][ASTR]
    float* Bs = sm + 128 * ASTR;       // [128][128]
    int tid = threadIdx.x;
    int tx = tid & 15, ty = tid >> 4;  // tx: col tile, ty: row tile
    int rb = blockIdx.x * 128;
    const float* B = (blockIdx.y == 0) ? W : g_M;

    // stage A (x rows rb..rb+127) and B (full 128x128)
    #pragma unroll
    for (int i = 0; i < 16; i++) {
        int f = i * 256 + tid;         // float4 index in [0,4096)
        int row = f >> 5, c4 = f & 31;
        float4 v = ((const float4*)x)[(rb + row) * 32 + c4];
        *((float4*)&As[row * ASTR + c4 * 4]) = v;
        ((float4*)Bs)[f] = ((const float4*)B)[f];
    }
    __syncthreads();

    int r0 = ty * 8, c0 = tx * 8;
    float acc[8][8] = {};
    #pragma unroll 8
    for (int k = 0; k < DIM; k++) {
        float a[8];
        #pragma unroll
        for (int i = 0; i < 8; i++) a[i] = As[(r0 + i) * ASTR + k];
        float4 b0 = ((float4*)Bs)[k * 32 + tx * 2];
        float4 b1 = ((float4*)Bs)[k * 32 + tx * 2 + 1];
        float b[8] = {b0.x, b0.y, b0.z, b0.w, b1.x, b1.y, b1.z, b1.w};
        #pragma unroll
        for (int i = 0; i < 8; i++)
            #pragma unroll
            for (int j = 0; j < 8; j++)
                acc[i][j] += a[i] * b[j];
    }

    if (blockIdx.y == 0) {
        #pragma unroll
        for (int i = 0; i < 8; i++) {
            int grow = rb + r0 + i;
            float s = g_dis[grow];
            float4 o0 = make_float4(acc[i][0]*s, acc[i][1]*s, acc[i][2]*s, acc[i][3]*s);
            float4 o1 = make_float4(acc[i][4]*s, acc[i][5]*s, acc[i][6]*s, acc[i][7]*s);
            ((float4*)g_dxw)[grow * 32 + tx * 2]     = o0;
            ((float4*)g_dxw)[grow * 32 + tx * 2 + 1] = o1;
        }
    } else {
        #pragma unroll
        for (int i = 0; i < 8; i++) {
            int grow = rb + r0 + i;
            float s = g_inv_nrm[grow];
            float o[8];
            #pragma unroll
            for (int j = 0; j < 8; j++)
                o[j] = 1.f / (1.f + __expf(-acc[i][j] * s));
            ((float4*)g_gate)[grow * 32 + tx * 2]     = make_float4(o[0], o[1], o[2], o[3]);
            ((float4*)g_gate)[grow * 32 + tx * 2 + 1] = make_float4(o[4], o[5], o[6], o[7]);
        }
    }
}

// ----------------- K7: CSR gather + precomputed gate + bias (warp per node)
__global__ void k_final(const float* __restrict__ b, float* __restrict__ out) {
    int tid = threadIdx.x;
    int w = tid >> 5, lane = tid & 31;
    int node = blockIdx.x * 8 + w;
    const float4* dxw4 = (const float4*)g_dxw;

    int s0  = g_start[node];
    int cnt = g_cnt[node];
    float4 acc = dxw4[node * 32 + lane];   // self loop
    int j = 0;
    for (; j + 4 <= cnt; j += 4) {
        int i0 = __ldg(&g_csr[s0 + j]);
        int i1 = __ldg(&g_csr[s0 + j + 1]);
        int i2 = __ldg(&g_csr[s0 + j + 2]);
        int i3 = __ldg(&g_csr[s0 + j + 3]);
        float4 v0 = dxw4[i0 * 32 + lane];
        float4 v1 = dxw4[i1 * 32 + lane];
        float4 v2 = dxw4[i2 * 32 + lane];
        float4 v3 = dxw4[i3 * 32 + lane];
        acc.x += v0.x + v1.x + v2.x + v3.x;
        acc.y += v0.y + v1.y + v2.y + v3.y;
        acc.z += v0.z + v1.z + v2.z + v3.z;
        acc.w += v0.w + v1.w + v2.w + v3.w;
    }
    for (; j < cnt; j++) {
        int i0 = __ldg(&g_csr[s0 + j]);
        float4 v0 = dxw4[i0 * 32 + lane];
        acc.x += v0.x; acc.y += v0.y; acc.z += v0.z; acc.w += v0.w;
    }
    float di = g_dis[node];
    float4 bb = ((const float4*)b)[lane];
    float4 a  = ((const float4*)g_gate)[node * 32 + lane];
    float4 o;
    o.x = (acc.x * di + bb.x) * a.x;
    o.y = (acc.y * di + bb.y) * a.y;
    o.z = (acc.z * di + bb.z) * a.z;
    o.w = (acc.w * di + bb.w) * a.w;
    ((float4*)out)[node * 32 + lane] = o;
}

// ---------------------------------------------------------------- launcher
extern "C" void kernel_launch(void* const* d_in, const int* in_sizes, int n_in,
                              void* d_out, int out_size) {
    const float* x  = (const float*)d_in[0];
    const int*   ei = (const int*)d_in[1];
    const float* W  = (const float*)d_in[2];
    const float* b  = (const float*)d_in[3];
    float* out = (float*)d_out;

    const int SMEM_G = (128 * ASTR + 128 * 128) * 4;   // ~131.6 KB
    cudaFuncSetAttribute(k_gemm, cudaFuncAttributeMaxDynamicSharedMemorySize, SMEM_G);

    k_setup<<<1024, 256>>>(x);
    k_hist<<<E / 256, 256>>>(ei);
    k_scan<<<1, 1024>>>();
    k_fill<<<E / 256, 256>>>(ei);
    k_maccum<<<128, 256>>>(x);
    k_gemm<<<dim3(64, 2), 256, SMEM_G>>>(x, W);
    k_final<<<N / 8, 256>>>(b, out);
}

// round 5
// speedup vs baseline: 1.8487x; 1.2815x over previous
#include <cuda_runtime.h>

#define N    8192
#define DIM  128
#define E    262144
#define NB   32          // CSR-build blocks
#define EPB  (E / NB)    // 8192 edges per block
#define ASTR 132         // padded A row stride (floats)

// Scratch (device globals -- allocation-free per harness rules)
__device__ float g_inv_nrm[N];
__device__ float g_dis[N];            // rsqrt(deg+1)
__device__ int   g_cnt[N];            // in-degree (excl. self loop)
__device__ int   g_start[N];          // CSR start offsets
__device__ int   g_part[NB * N];      // per-block partial histograms
__device__ int   g_bstart[NB * N];    // per-block fill base offsets
__device__ int   g_csr[E];            // CSR: source node per slot
__device__ float g_M[DIM * DIM];      // Y^T x
__device__ float g_dxw[N * DIM];      // x @ W   (UNSCALED)
__device__ float g_gate[N * DIM];     // sigmoid(y . M)

// ----------------- chain B1: per-block histogram in smem, spill partials
__global__ void k_hist(const int* __restrict__ ei) {
    __shared__ int sc[N];
    int tid = threadIdx.x;
    for (int i = tid; i < N / 4; i += 256) ((int4*)sc)[i] = make_int4(0, 0, 0, 0);
    __syncthreads();
    const int4* c4 = (const int4*)(ei + E) + blockIdx.x * (EPB / 4);
    for (int i = tid; i < EPB / 4; i += 256) {
        int4 c = c4[i];
        atomicAdd(&sc[c.x], 1); atomicAdd(&sc[c.y], 1);
        atomicAdd(&sc[c.z], 1); atomicAdd(&sc[c.w], 1);
    }
    __syncthreads();
    int4* out = (int4*)(g_part + blockIdx.x * N);
    for (int i = tid; i < N / 4; i += 256) out[i] = ((int4*)sc)[i];
}

// ----------------- chain B2: reduce partials -> cnt, dis (coalesced)
__global__ void k_reduce() {
    int node = blockIdx.x * 256 + threadIdx.x;
    int s = 0;
    #pragma unroll
    for (int b = 0; b < NB; b++) s += g_part[b * N + node];
    g_cnt[node] = s;
    g_dis[node] = rsqrtf((float)(s + 1));
}

// ----------------- chain B3: exclusive scan over 8192 counts (1 block)
__global__ void k_scan() {
    __shared__ int warp_sums[32];
    int tid = threadIdx.x;            // 1024 threads, 8 counters each
    int base = tid * 8;
    int c[8], s = 0;
    #pragma unroll
    for (int j = 0; j < 8; j++) { c[j] = g_cnt[base + j]; s += c[j]; }
    int lane = tid & 31, w = tid >> 5;
    int v = s;
    #pragma unroll
    for (int o = 1; o < 32; o <<= 1) {
        int t = __shfl_up_sync(0xffffffffu, v, o);
        if (lane >= o) v += t;
    }
    if (lane == 31) warp_sums[w] = v;
    __syncthreads();
    if (w == 0) {
        int ws = warp_sums[lane];
        #pragma unroll
        for (int o = 1; o < 32; o <<= 1) {
            int t = __shfl_up_sync(0xffffffffu, ws, o);
            if (lane >= o) ws += t;
        }
        warp_sums[lane] = ws;
    }
    __syncthreads();
    int run = v - s + (w > 0 ? warp_sums[w - 1] : 0);
    #pragma unroll
    for (int j = 0; j < 8; j++) { g_start[base + j] = run; run += c[j]; }
}

// ----------------- chain B4: per-block fill bases (coalesced)
__global__ void k_bstart() {
    int node = blockIdx.x * 256 + threadIdx.x;
    int run = g_start[node];
    #pragma unroll
    for (int b = 0; b < NB; b++) {
        g_bstart[b * N + node] = run;
        run += g_part[b * N + node];
    }
}

// ----------------- chain B5: CSR fill with SMEM cursors (no global atomics)
__global__ void k_fill(const int* __restrict__ ei) {
    __shared__ int cur[N];
    int tid = threadIdx.x;
    const int4* bs4 = (const int4*)(g_bstart + blockIdx.x * N);
    for (int i = tid; i < N / 4; i += 256) ((int4*)cur)[i] = bs4[i];
    __syncthreads();
    const int4* r4 = (const int4*)ei + blockIdx.x * (EPB / 4);
    const int4* c4 = (const int4*)(ei + E) + blockIdx.x * (EPB / 4);
    for (int i = tid; i < EPB / 4; i += 256) {
        int4 r = r4[i];
        int4 c = c4[i];
        g_csr[atomicAdd(&cur[c.x], 1)] = r.x;
        g_csr[atomicAdd(&cur[c.y], 1)] = r.y;
        g_csr[atomicAdd(&cur[c.z], 1)] = r.z;
        g_csr[atomicAdd(&cur[c.w], 1)] = r.w;
    }
}

// ----------------- main A1: row inverse norms + zero M
__global__ void k_norms(const float* __restrict__ x) {
    int tid = threadIdx.x;
    int gi = blockIdx.x * 256 + tid;
    if (gi < DIM * DIM) g_M[gi] = 0.f;
    int w = tid >> 5, lane = tid & 31;
    int row = blockIdx.x * 8 + w;
    float4 v = ((const float4*)x)[row * 32 + lane];
    float s = v.x * v.x + v.y * v.y + v.z * v.z + v.w * v.w;
    #pragma unroll
    for (int o = 16; o; o >>= 1) s += __shfl_xor_sync(0xffffffffu, s, o);
    if (lane == 0) g_inv_nrm[row] = rsqrtf(s);
}

// ----------------- main A2: M = Y^T x (128x128), 8x8 tiles + atomics
__global__ void k_maccum(const float* __restrict__ x) {
    __shared__ float xs[8][DIM];
    __shared__ float invs[8];
    int tid = threadIdx.x;
    int tx = tid & 15, ty = tid >> 4;
    int k0 = ty * 8, d0 = tx * 8;
    float acc[8][8] = {};
    int row_base = blockIdx.x * 64;
    for (int p = 0; p < 8; p++) {
        int r0 = row_base + p * 8;
        {
            int rr = tid >> 5, cc = tid & 31;
            float4 v = ((const float4*)x)[(r0 + rr) * 32 + cc];
            ((float4*)&xs[rr][0])[cc] = v;
        }
        if (tid < 8) invs[tid] = g_inv_nrm[r0 + tid];
        __syncthreads();
        #pragma unroll
        for (int r = 0; r < 8; r++) {
            float inv = invs[r];
            float yk[8], xd[8];
            #pragma unroll
            for (int j = 0; j < 8; j++) yk[j] = xs[r][k0 + j] * inv;
            #pragma unroll
            for (int l = 0; l < 8; l++) xd[l] = xs[r][d0 + l];
            #pragma unroll
            for (int j = 0; j < 8; j++)
                #pragma unroll
                for (int l = 0; l < 8; l++)
                    acc[j][l] += yk[j] * xd[l];
        }
        __syncthreads();
    }
    #pragma unroll
    for (int j = 0; j < 8; j++)
        #pragma unroll
        for (int l = 0; l < 8; l++)
            atomicAdd(&g_M[(k0 + j) * DIM + (d0 + l)], acc[j][l]);
}

// ----------------- GEMM P = x @ B, 128x128 tile, 8x8/thread
// mode 0: B=W   -> g_dxw  (unscaled)
// mode 1: B=g_M -> g_gate = sigmoid(P * inv_nrm[row])
__global__ void k_gemm(const float* __restrict__ x, const float* __restrict__ Bp,
                       int mode) {
    extern __shared__ float sm[];
    float* As = sm;                    // [128][ASTR]
    float* Bs = sm + 128 * ASTR;       // [128][128]
    int tid = threadIdx.x;
    int tx = tid & 15, ty = tid >> 4;
    int rb = blockIdx.x * 128;
    const float* B = (mode == 0) ? Bp : g_M;

    #pragma unroll
    for (int i = 0; i < 16; i++) {
        int f = i * 256 + tid;
        int row = f >> 5, c4 = f & 31;
        float4 v = ((const float4*)x)[(rb + row) * 32 + c4];
        *((float4*)&As[row * ASTR + c4 * 4]) = v;
        ((float4*)Bs)[f] = ((const float4*)B)[f];
    }
    __syncthreads();

    int r0 = ty * 8;
    float acc[8][8] = {};
    #pragma unroll 8
    for (int k = 0; k < DIM; k++) {
        float a[8];
        #pragma unroll
        for (int i = 0; i < 8; i++) a[i] = As[(r0 + i) * ASTR + k];
        float4 b0 = ((float4*)Bs)[k * 32 + tx * 2];
        float4 b1 = ((float4*)Bs)[k * 32 + tx * 2 + 1];
        float b[8] = {b0.x, b0.y, b0.z, b0.w, b1.x, b1.y, b1.z, b1.w};
        #pragma unroll
        for (int i = 0; i < 8; i++)
            #pragma unroll
            for (int j = 0; j < 8; j++)
                acc[i][j] += a[i] * b[j];
    }

    if (mode == 0) {
        #pragma unroll
        for (int i = 0; i < 8; i++) {
            int grow = rb + r0 + i;
            ((float4*)g_dxw)[grow * 32 + tx * 2] =
                make_float4(acc[i][0], acc[i][1], acc[i][2], acc[i][3]);
            ((float4*)g_dxw)[grow * 32 + tx * 2 + 1] =
                make_float4(acc[i][4], acc[i][5], acc[i][6], acc[i][7]);
        }
    } else {
        #pragma unroll
        for (int i = 0; i < 8; i++) {
            int grow = rb + r0 + i;
            float s = g_inv_nrm[grow];
            float o[8];
            #pragma unroll
            for (int j = 0; j < 8; j++)
                o[j] = 1.f / (1.f + __expf(-acc[i][j] * s));
            ((float4*)g_gate)[grow * 32 + tx * 2]     = make_float4(o[0], o[1], o[2], o[3]);
            ((float4*)g_gate)[grow * 32 + tx * 2 + 1] = make_float4(o[4], o[5], o[6], o[7]);
        }
    }
}

// ----------------- join: CSR gather (dis[src] applied here) + gate + bias
__global__ void k_final(const float* __restrict__ b, float* __restrict__ out) {
    int tid = threadIdx.x;
    int w = tid >> 5, lane = tid & 31;
    int node = blockIdx.x * 8 + w;
    const float4* dxw4 = (const float4*)g_dxw;

    int s0  = g_start[node];
    int cnt = g_cnt[node];
    float dn = g_dis[node];
    float4 self = dxw4[node * 32 + lane];
    float4 acc;
    acc.x = self.x * dn; acc.y = self.y * dn;
    acc.z = self.z * dn; acc.w = self.w * dn;
    int j = 0;
    for (; j + 4 <= cnt; j += 4) {
        int i0 = __ldg(&g_csr[s0 + j]);
        int i1 = __ldg(&g_csr[s0 + j + 1]);
        int i2 = __ldg(&g_csr[s0 + j + 2]);
        int i3 = __ldg(&g_csr[s0 + j + 3]);
        float d0 = __ldg(&g_dis[i0]), d1 = __ldg(&g_dis[i1]);
        float d2 = __ldg(&g_dis[i2]), d3 = __ldg(&g_dis[i3]);
        float4 v0 = dxw4[i0 * 32 + lane];
        float4 v1 = dxw4[i1 * 32 + lane];
        float4 v2 = dxw4[i2 * 32 + lane];
        float4 v3 = dxw4[i3 * 32 + lane];
        acc.x += v0.x * d0 + v1.x * d1 + v2.x * d2 + v3.x * d3;
        acc.y += v0.y * d0 + v1.y * d1 + v2.y * d2 + v3.y * d3;
        acc.z += v0.z * d0 + v1.z * d1 + v2.z * d2 + v3.z * d3;
        acc.w += v0.w * d0 + v1.w * d1 + v2.w * d2 + v3.w * d3;
    }
    for (; j < cnt; j++) {
        int i0 = __ldg(&g_csr[s0 + j]);
        float d0 = __ldg(&g_dis[i0]);
        float4 v0 = dxw4[i0 * 32 + lane];
        acc.x += v0.x * d0; acc.y += v0.y * d0;
        acc.z += v0.z * d0; acc.w += v0.w * d0;
    }
    float4 bb = ((const float4*)b)[lane];
    float4 a  = ((const float4*)g_gate)[node * 32 + lane];
    float4 o;
    o.x = (acc.x * dn + bb.x) * a.x;
    o.y = (acc.y * dn + bb.y) * a.y;
    o.z = (acc.z * dn + bb.z) * a.z;
    o.w = (acc.w * dn + bb.w) * a.w;
    ((float4*)out)[node * 32 + lane] = o;
}

// ---------------------------------------------------------------- launcher
extern "C" void kernel_launch(void* const* d_in, const int* in_sizes, int n_in,
                              void* d_out, int out_size) {
    const float* x  = (const float*)d_in[0];
    const int*   ei = (const int*)d_in[1];
    const float* W  = (const float*)d_in[2];
    const float* b  = (const float*)d_in[3];
    float* out = (float*)d_out;

    static bool init_done = false;
    static cudaStream_t sB, sC;
    static cudaEvent_t evRoot, evB, evC;
    if (!init_done) {
        cudaStreamCreateWithFlags(&sB, cudaStreamNonBlocking);
        cudaStreamCreateWithFlags(&sC, cudaStreamNonBlocking);
        cudaEventCreateWithFlags(&evRoot, cudaEventDisableTiming);
        cudaEventCreateWithFlags(&evB,    cudaEventDisableTiming);
        cudaEventCreateWithFlags(&evC,    cudaEventDisableTiming);
        const int SMEM_G = (128 * ASTR + 128 * 128) * 4;
        cudaFuncSetAttribute(k_gemm, cudaFuncAttributeMaxDynamicSharedMemorySize, SMEM_G);
        init_done = true;
    }
    const int SMEM_G = (128 * ASTR + 128 * 128) * 4;

    // fork
    cudaEventRecord(evRoot, 0);
    cudaStreamWaitEvent(sB, evRoot, 0);
    cudaStreamWaitEvent(sC, evRoot, 0);

    // chain B: CSR build (latency-bound; overlaps compute chains)
    k_hist  <<<NB, 256, 0, sB>>>(ei);
    k_reduce<<<N / 256, 256, 0, sB>>>();
    k_scan  <<<1, 1024, 0, sB>>>();
    k_bstart<<<N / 256, 256, 0, sB>>>();
    k_fill  <<<NB, 256, 0, sB>>>(ei);
    cudaEventRecord(evB, sB);

    // chain C: x @ W (no dependencies)
    k_gemm<<<64, 256, SMEM_G, sC>>>(x, W, 0);
    cudaEventRecord(evC, sC);

    // main chain: norms -> M -> gate
    k_norms <<<N / 8, 256>>>(x);
    k_maccum<<<128, 256>>>(x);
    k_gemm  <<<64, 256, SMEM_G>>>(x, nullptr, 1);

    // join
    cudaStreamWaitEvent(0, evB, 0);
    cudaStreamWaitEvent(0, evC, 0);
    k_final<<<N / 8, 256>>>(b, out);
}